// round 2
// baseline (speedup 1.0000x reference)
#include <cuda_runtime.h>

// ---------------------------------------------------------------------------
// SymmetricContraction: out[b,c,m] = cubic polynomial in A[b,c,0..8]
// Stage 1 (symU):   Usym[t][m][k]  = perm-symmetrized U, c-independent (tiny)
// Stage 2 (buildS): S[c][t][m]     = sum_k Usym[t][m][k] * w_k[c]
// Stage 3 (main):   out[b,c,m]     = sum_t S[c][t][m] * mono_t(A[b,c,:])
//   4 nodes per thread -> each smem row load feeds 36 FMAs (was 9).
// ---------------------------------------------------------------------------

#define NC 128        // channels
#define NB 2048       // nodes
#define NI 9          // irreps dim
#define NT 219        // 9 singles + 45 pairs + 165 triples
#define ROWP 12       // padded row (floats) -> 48B
#define NBT 4         // nodes per thread

static __device__ float g_S[NC * NT * ROWP];       // ~1.35 MB
static __device__ float g_sym2[45 * 9 * 4];        // deg-2 symmetrized U (k-padded to 4)
static __device__ float g_sym3[165 * 9 * 10];      // deg-3 symmetrized U (k-padded to 10)

// ---------------------------------------------------------------------------
// Kernel A: symmetrize U over index permutations (c-independent, tiny)
// ---------------------------------------------------------------------------
__global__ void symU_kernel(
    const float* __restrict__ Us2, const float* __restrict__ Up2, const float* __restrict__ Ud2,
    const float* __restrict__ Us3, const float* __restrict__ Up3, const float* __restrict__ Ud3)
{
    int gid = blockIdx.x * blockDim.x + threadIdx.x;

    if (gid < 45 * 9) {
        // degree-2 job: (pair tp, output m)
        int m = gid % 9, tp = gid / 9;
        int rem = tp, i = 0, j = 0;
        for (i = 0; i < 9; i++) { int cnt = 9 - i; if (rem < cnt) { j = i + rem; break; } rem -= cnt; }
        int pa[2] = { i, j }, pb[2] = { j, i };
        float inv = (i == j) ? 0.5f : 1.0f;

        int K; const float* U; int mm;
        if (m == 0)      { K = 2; U = Us2; mm = 0; }
        else if (m < 4)  { K = 3; U = Up2; mm = m - 1; }
        else             { K = 4; U = Ud2; mm = m - 4; }

        for (int k = 0; k < 4; k++) {
            float s = 0.f;
            if (k < K)
                for (int p = 0; p < 2; p++)
                    s += U[((mm * 9 + pa[p]) * 9 + pb[p]) * K + k];
            g_sym2[(tp * 9 + m) * 4 + k] = s * inv;
        }
    } else if (gid < 45 * 9 + 165 * 9) {
        // degree-3 job: (triple tp, output m)
        int j2 = gid - 45 * 9;
        int m = j2 % 9, tp = j2 / 9;
        int rem = tp, i = 0, j = 0, l = 0;
        for (i = 0; i < 9; i++) { int cnt = (9 - i) * (10 - i) / 2; if (rem < cnt) break; rem -= cnt; }
        for (j = i; j < 9; j++) { int cnt = 9 - j; if (rem < cnt) { l = j + rem; break; } rem -= cnt; }
        float inv;
        if (i == j && j == l)                 inv = 1.0f / 6.0f;
        else if (i == j || j == l || i == l)  inv = 0.5f;
        else                                  inv = 1.0f;
        int P0[6] = { i,i,j,j,l,l }, P1[6] = { j,l,i,l,i,j }, P2i[6] = { l,j,l,i,j,i };

        int K; const float* U; int mm;
        if (m == 0)      { K = 5;  U = Us3; mm = 0; }
        else if (m < 4)  { K = 8;  U = Up3; mm = m - 1; }
        else             { K = 10; U = Ud3; mm = m - 4; }

        for (int k = 0; k < 10; k++) {
            float s = 0.f;
            if (k < K)
                for (int p = 0; p < 6; p++)
                    s += U[(((mm * 9 + P0[p]) * 9 + P1[p]) * 9 + P2i[p]) * K + k];
            g_sym3[(tp * 9 + m) * 10 + k] = s * inv;
        }
    }
}

// ---------------------------------------------------------------------------
// Kernel B: contract symmetrized U with w -> S[c][t][0..8]
// gid t-major: warp-uniform sym loads (broadcast), coalesced w loads over c.
// ---------------------------------------------------------------------------
__global__ void buildS_kernel(
    const float* __restrict__ Us1, const float* __restrict__ Up1, const float* __restrict__ Ud1,
    const float* __restrict__ ws1, const float* __restrict__ ws2, const float* __restrict__ ws3,
    const float* __restrict__ wp1, const float* __restrict__ wp2, const float* __restrict__ wp3,
    const float* __restrict__ wd1, const float* __restrict__ wd2, const float* __restrict__ wd3)
{
    int gid = blockIdx.x * blockDim.x + threadIdx.x;
    if (gid >= NT * NC) return;
    int t = gid / NC;
    int c = gid % NC;

    float v[9];

    if (t < 9) {
        v[0] = Us1[t] * ws1[c];
#pragma unroll
        for (int m = 0; m < 3; m++) v[1 + m] = Up1[m * 9 + t] * wp1[c];
#pragma unroll
        for (int m = 0; m < 5; m++) v[4 + m] = Ud1[m * 9 + t] * wd1[c];
    } else if (t < 54) {
        int tp = t - 9;
        {
            float s = 0.f;
            for (int k = 0; k < 2; k++) s += g_sym2[(tp * 9 + 0) * 4 + k] * ws2[k * NC + c];
            v[0] = s;
        }
#pragma unroll
        for (int m = 1; m < 4; m++) {
            float s = 0.f;
            for (int k = 0; k < 3; k++) s += g_sym2[(tp * 9 + m) * 4 + k] * wp2[k * NC + c];
            v[m] = s;
        }
#pragma unroll
        for (int m = 4; m < 9; m++) {
            float s = 0.f;
            for (int k = 0; k < 4; k++) s += g_sym2[(tp * 9 + m) * 4 + k] * wd2[k * NC + c];
            v[m] = s;
        }
    } else {
        int tp = t - 54;
        {
            float s = 0.f;
            for (int k = 0; k < 5; k++) s += g_sym3[(tp * 9 + 0) * 10 + k] * ws3[k * NC + c];
            v[0] = s;
        }
#pragma unroll
        for (int m = 1; m < 4; m++) {
            float s = 0.f;
            for (int k = 0; k < 8; k++) s += g_sym3[(tp * 9 + m) * 10 + k] * wp3[k * NC + c];
            v[m] = s;
        }
#pragma unroll
        for (int m = 4; m < 9; m++) {
            float s = 0.f;
            for (int k = 0; k < 10; k++) s += g_sym3[(tp * 9 + m) * 10 + k] * wd3[k * NC + c];
            v[m] = s;
        }
    }

    float* dst = g_S + (c * NT + t) * ROWP;
#pragma unroll
    for (int q = 0; q < 9; q++) dst[q] = v[q];
    dst[9] = 0.f; dst[10] = 0.f; dst[11] = 0.f;
}

// ---------------------------------------------------------------------------
// Kernel C: hot loop. One block-column per channel c; 4 nodes per thread.
// Every smem row load (broadcast, conflict-free) feeds 36 FMAs.
// ---------------------------------------------------------------------------
__device__ __forceinline__ void fma9x4(float acc[NBT][9], const float* __restrict__ row,
                                       const float m4[NBT])
{
    float4 r0 = *reinterpret_cast<const float4*>(row);
    float4 r1 = *reinterpret_cast<const float4*>(row + 4);
    float  r8 = row[8];
#pragma unroll
    for (int n = 0; n < NBT; n++) {
        acc[n][0] = fmaf(r0.x, m4[n], acc[n][0]);
        acc[n][1] = fmaf(r0.y, m4[n], acc[n][1]);
        acc[n][2] = fmaf(r0.z, m4[n], acc[n][2]);
        acc[n][3] = fmaf(r0.w, m4[n], acc[n][3]);
        acc[n][4] = fmaf(r1.x, m4[n], acc[n][4]);
        acc[n][5] = fmaf(r1.y, m4[n], acc[n][5]);
        acc[n][6] = fmaf(r1.z, m4[n], acc[n][6]);
        acc[n][7] = fmaf(r1.w, m4[n], acc[n][7]);
        acc[n][8] = fmaf(r8,  m4[n], acc[n][8]);
    }
}

__global__ __launch_bounds__(256) void sc_main_kernel(
    const float* __restrict__ A, float* __restrict__ out)
{
    __shared__ __align__(16) float sS[NT * ROWP];

    int c = blockIdx.x;
    const float* gS = g_S + c * NT * ROWP;
    for (int idx = threadIdx.x; idx < NT * ROWP; idx += 256)
        sS[idx] = gS[idx];
    __syncthreads();

    int bbase = blockIdx.y * (256 * NBT) + threadIdx.x;   // nodes bbase + n*256

    float a[NBT][9];
#pragma unroll
    for (int n = 0; n < NBT; n++) {
        const float* Ap = A + ((bbase + n * 256) * NC + c) * NI;
#pragma unroll
        for (int i = 0; i < 9; i++) a[n][i] = __ldg(Ap + i);
    }

    float acc[NBT][9];
#pragma unroll
    for (int n = 0; n < NBT; n++)
#pragma unroll
        for (int q = 0; q < 9; q++) acc[n][q] = 0.f;

    // ---- degree 1: rows 0..8
#pragma unroll
    for (int i = 0; i < 9; i++) {
        float m4[NBT];
#pragma unroll
        for (int n = 0; n < NBT; n++) m4[n] = a[n][i];
        fma9x4(acc, sS + i * ROWP, m4);
    }

    // ---- degree 2 (rows 9..53) + degree 3 (rows 54..218)
    int trow = 54;                                        // folded by full unroll
#pragma unroll
    for (int i = 0; i < 9; i++) {
#pragma unroll
        for (int j = i; j < 9; j++) {
            int pidx = i * 9 - (i * (i - 1)) / 2 + (j - i);
            float p4[NBT];
#pragma unroll
            for (int n = 0; n < NBT; n++) p4[n] = a[n][i] * a[n][j];
            fma9x4(acc, sS + (9 + pidx) * ROWP, p4);
#pragma unroll
            for (int l = j; l < 9; l++) {
                float m4[NBT];
#pragma unroll
                for (int n = 0; n < NBT; n++) m4[n] = p4[n] * a[n][l];
                fma9x4(acc, sS + trow * ROWP, m4);
                trow++;
            }
        }
    }

#pragma unroll
    for (int n = 0; n < NBT; n++) {
        float* op = out + ((bbase + n * 256) * NC + c) * NI;
#pragma unroll
        for (int q = 0; q < 9; q++) op[q] = acc[n][q];
    }
}

// ---------------------------------------------------------------------------
// Launch: resolve inputs by element count (ordering-agnostic).
// ---------------------------------------------------------------------------
extern "C" void kernel_launch(void* const* d_in, const int* in_sizes, int n_in,
                              void* d_out, int out_size)
{
    const float* A = nullptr;
    const float* U[3][3] = {};   // [type s/p/d][nu-1]
    const float* W[3][3] = {};   // [type s/p/d][nu-1]

    int typeorder[3] = { 0, 1, 2 };
    int to_n = 0;
    int w1_idx[3]; int w1_n = 0;

    for (int idx = 0; idx < n_in; idx++) {
        int s = in_sizes[idx];
        const float* p = (const float*)d_in[idx];
        switch (s) {
            case NB * NC * NI: A = p; break;
            case 9:     U[0][0] = p; break;   // U_s1 (1,9,1)
            case 162:   U[0][1] = p; break;   // U_s2 (1,9,9,2)
            case 3645:  U[0][2] = p; break;   // U_s3 (1,9,9,9,5)
            case 27:    U[1][0] = p; break;   // U_p1 (3,9,1)
            case 729:   U[1][1] = p; break;   // U_p2 (3,9,9,3)
            case 17496: U[1][2] = p; break;   // U_p3 (3,9,9,9,8)
            case 45:    U[2][0] = p; break;   // U_d1 (5,9,1)
            case 1620:  U[2][1] = p; break;   // U_d2 (5,9,9,4)
            case 36450: U[2][2] = p; break;   // U_d3 (5,9,9,9,10)
            case 256:   W[0][1] = p; if (to_n < 3) typeorder[to_n++] = 0; break; // w_s2
            case 384:   W[1][1] = p; if (to_n < 3) typeorder[to_n++] = 1; break; // w_p2
            case 512:   W[2][1] = p; if (to_n < 3) typeorder[to_n++] = 2; break; // w_d2
            case 640:   W[0][2] = p; break;   // w_s3
            case 1024:  W[1][2] = p; break;   // w_p3
            case 1280:  W[2][2] = p; break;   // w_d3
            case 128:   if (w1_n < 3) w1_idx[w1_n++] = idx; break; // w_*1 (ambiguous)
            default: break;
        }
    }
    for (int q = 0; q < 3 && q < w1_n; q++)
        W[typeorder[q]][0] = (const float*)d_in[w1_idx[q]];

    // Stage 1: symmetrize U (c-independent)
    {
        int jobs = 45 * 9 + 165 * 9;
        symU_kernel<<<(jobs + 255) / 256, 256>>>(
            U[0][1], U[1][1], U[2][1],
            U[0][2], U[1][2], U[2][2]);
    }

    // Stage 2: contract with w -> per-channel S
    {
        int jobs = NT * NC;
        buildS_kernel<<<(jobs + 255) / 256, 256>>>(
            U[0][0], U[1][0], U[2][0],
            W[0][0], W[0][1], W[0][2],
            W[1][0], W[1][1], W[1][2],
            W[2][0], W[2][1], W[2][2]);
    }

    // Stage 3: main contraction, 4 nodes per thread
    dim3 grid(NC, NB / (256 * NBT));
    sc_main_kernel<<<grid, 256>>>(A, (float*)d_out);
}

// round 3
// speedup vs baseline: 1.0648x; 1.0648x over previous
#include <cuda_runtime.h>

// ---------------------------------------------------------------------------
// SymmetricContraction: out[b,c,m] = cubic polynomial in A[b,c,0..8]
// Stage 1 (symU):   Usym[t][m][k]  = perm-symmetrized U, c-independent (tiny)
//                   parallel over (t,m,k): each thread sums 2 or 6 values.
// Stage 2 (buildS): S[c][t][m]     = sum_k Usym[t][m][k] * w_k[c]
// Stage 3 (main):   out[b,c,m]     = sum_t S[c][t][m] * mono_t(A[b,c,:])
//   64-thread blocks, 4 nodes/thread -> 1024 blocks (balanced), each smem
//   row load (broadcast, conflict-free) feeds 36 FMAs.
// ---------------------------------------------------------------------------

#define NC 128        // channels
#define NB 2048       // nodes
#define NI 9          // irreps dim
#define NT 219        // 9 singles + 45 pairs + 165 triples
#define ROWP 12       // padded row (floats) -> 48B
#define NBT 4         // nodes per thread
#define BLK 64        // threads per main block

static __device__ float g_S[NC * NT * ROWP];       // ~1.35 MB
static __device__ float g_sym2[45 * 9 * 4];        // deg-2 symmetrized U (k-pad 4)
static __device__ float g_sym3[165 * 9 * 10];      // deg-3 symmetrized U (k-pad 10)

// ---------------------------------------------------------------------------
// Kernel A: symmetrize U. One thread per OUTPUT SCALAR (t,m,k) -> 2/6 loads.
// ---------------------------------------------------------------------------
__global__ void symU_kernel(
    const float* __restrict__ Us2, const float* __restrict__ Up2, const float* __restrict__ Ud2,
    const float* __restrict__ Us3, const float* __restrict__ Up3, const float* __restrict__ Ud3)
{
    int gid = blockIdx.x * blockDim.x + threadIdx.x;

    if (gid < 45 * 9 * 4) {
        // degree-2: gid = (tp*9 + m)*4 + k
        int k = gid % 4; int r = gid / 4;
        int m = r % 9;   int tp = r / 9;
        int rem = tp, i = 0, j = 0;
        for (i = 0; i < 9; i++) { int cnt = 9 - i; if (rem < cnt) { j = i + rem; break; } rem -= cnt; }
        float inv = (i == j) ? 0.5f : 1.0f;

        int K; const float* U; int mm;
        if (m == 0)      { K = 2; U = Us2; mm = 0; }
        else if (m < 4)  { K = 3; U = Up2; mm = m - 1; }
        else             { K = 4; U = Ud2; mm = m - 4; }

        float s = 0.f;
        if (k < K)
            s = U[((mm * 9 + i) * 9 + j) * K + k] + U[((mm * 9 + j) * 9 + i) * K + k];
        g_sym2[gid] = s * inv;
    } else if (gid < 45 * 9 * 4 + 165 * 9 * 10) {
        // degree-3: gid2 = (tp*9 + m)*10 + k
        int g2 = gid - 45 * 9 * 4;
        int k = g2 % 10; int r = g2 / 10;
        int m = r % 9;   int tp = r / 9;
        int rem = tp, i = 0, j = 0, l = 0;
        for (i = 0; i < 9; i++) { int cnt = (9 - i) * (10 - i) / 2; if (rem < cnt) break; rem -= cnt; }
        for (j = i; j < 9; j++) { int cnt = 9 - j; if (rem < cnt) { l = j + rem; break; } rem -= cnt; }
        float inv;
        if (i == j && j == l)                 inv = 1.0f / 6.0f;
        else if (i == j || j == l || i == l)  inv = 0.5f;
        else                                  inv = 1.0f;

        int K; const float* U; int mm;
        if (m == 0)      { K = 5;  U = Us3; mm = 0; }
        else if (m < 4)  { K = 8;  U = Up3; mm = m - 1; }
        else             { K = 10; U = Ud3; mm = m - 4; }

        float s = 0.f;
        if (k < K) {
            int P0[6] = { i,i,j,j,l,l }, P1[6] = { j,l,i,l,i,j }, P2i[6] = { l,j,l,i,j,i };
#pragma unroll
            for (int p = 0; p < 6; p++)
                s += U[(((mm * 9 + P0[p]) * 9 + P1[p]) * 9 + P2i[p]) * K + k];
        }
        g_sym3[g2] = s * inv;
    }
}

// ---------------------------------------------------------------------------
// Kernel B: contract symmetrized U with w -> S[c][t][0..8]
// gid t-major: warp-uniform sym loads (L2-broadcast), coalesced w loads over c.
// ---------------------------------------------------------------------------
__global__ void buildS_kernel(
    const float* __restrict__ Us1, const float* __restrict__ Up1, const float* __restrict__ Ud1,
    const float* __restrict__ ws1, const float* __restrict__ ws2, const float* __restrict__ ws3,
    const float* __restrict__ wp1, const float* __restrict__ wp2, const float* __restrict__ wp3,
    const float* __restrict__ wd1, const float* __restrict__ wd2, const float* __restrict__ wd3)
{
    int gid = blockIdx.x * blockDim.x + threadIdx.x;
    if (gid >= NT * NC) return;
    int t = gid / NC;
    int c = gid % NC;

    float v[9];

    if (t < 9) {
        v[0] = Us1[t] * ws1[c];
#pragma unroll
        for (int m = 0; m < 3; m++) v[1 + m] = Up1[m * 9 + t] * wp1[c];
#pragma unroll
        for (int m = 0; m < 5; m++) v[4 + m] = Ud1[m * 9 + t] * wd1[c];
    } else if (t < 54) {
        int tp = t - 9;
        {
            float s = 0.f;
            for (int k = 0; k < 2; k++) s += g_sym2[(tp * 9 + 0) * 4 + k] * ws2[k * NC + c];
            v[0] = s;
        }
#pragma unroll
        for (int m = 1; m < 4; m++) {
            float s = 0.f;
            for (int k = 0; k < 3; k++) s += g_sym2[(tp * 9 + m) * 4 + k] * wp2[k * NC + c];
            v[m] = s;
        }
#pragma unroll
        for (int m = 4; m < 9; m++) {
            float s = 0.f;
            for (int k = 0; k < 4; k++) s += g_sym2[(tp * 9 + m) * 4 + k] * wd2[k * NC + c];
            v[m] = s;
        }
    } else {
        int tp = t - 54;
        {
            float s = 0.f;
            for (int k = 0; k < 5; k++) s += g_sym3[(tp * 9 + 0) * 10 + k] * ws3[k * NC + c];
            v[0] = s;
        }
#pragma unroll
        for (int m = 1; m < 4; m++) {
            float s = 0.f;
            for (int k = 0; k < 8; k++) s += g_sym3[(tp * 9 + m) * 10 + k] * wp3[k * NC + c];
            v[m] = s;
        }
#pragma unroll
        for (int m = 4; m < 9; m++) {
            float s = 0.f;
            for (int k = 0; k < 10; k++) s += g_sym3[(tp * 9 + m) * 10 + k] * wd3[k * NC + c];
            v[m] = s;
        }
    }

    float* dst = g_S + (c * NT + t) * ROWP;
#pragma unroll
    for (int q = 0; q < 9; q++) dst[q] = v[q];
    dst[9] = 0.f; dst[10] = 0.f; dst[11] = 0.f;
}

// ---------------------------------------------------------------------------
// Kernel C: hot loop. 64-thread blocks, 4 nodes/thread, grid (128, 8).
// ---------------------------------------------------------------------------
__device__ __forceinline__ void fma9x4(float acc[NBT][9], const float* __restrict__ row,
                                       const float m4[NBT])
{
    float4 r0 = *reinterpret_cast<const float4*>(row);
    float4 r1 = *reinterpret_cast<const float4*>(row + 4);
    float  r8 = row[8];
#pragma unroll
    for (int n = 0; n < NBT; n++) {
        acc[n][0] = fmaf(r0.x, m4[n], acc[n][0]);
        acc[n][1] = fmaf(r0.y, m4[n], acc[n][1]);
        acc[n][2] = fmaf(r0.z, m4[n], acc[n][2]);
        acc[n][3] = fmaf(r0.w, m4[n], acc[n][3]);
        acc[n][4] = fmaf(r1.x, m4[n], acc[n][4]);
        acc[n][5] = fmaf(r1.y, m4[n], acc[n][5]);
        acc[n][6] = fmaf(r1.z, m4[n], acc[n][6]);
        acc[n][7] = fmaf(r1.w, m4[n], acc[n][7]);
        acc[n][8] = fmaf(r8,  m4[n], acc[n][8]);
    }
}

__global__ __launch_bounds__(BLK) void sc_main_kernel(
    const float* __restrict__ A, float* __restrict__ out)
{
    __shared__ __align__(16) float sS[NT * ROWP];

    int c = blockIdx.x;
    const float* gS = g_S + c * NT * ROWP;
    for (int idx = threadIdx.x; idx < NT * ROWP; idx += BLK)
        sS[idx] = gS[idx];
    __syncthreads();

    int bbase = blockIdx.y * (BLK * NBT) + threadIdx.x;   // nodes bbase + n*BLK

    float a[NBT][9];
#pragma unroll
    for (int n = 0; n < NBT; n++) {
        const float* Ap = A + ((bbase + n * BLK) * NC + c) * NI;
#pragma unroll
        for (int i = 0; i < 9; i++) a[n][i] = __ldg(Ap + i);
    }

    float acc[NBT][9];
#pragma unroll
    for (int n = 0; n < NBT; n++)
#pragma unroll
        for (int q = 0; q < 9; q++) acc[n][q] = 0.f;

    // ---- degree 1: rows 0..8
#pragma unroll
    for (int i = 0; i < 9; i++) {
        float m4[NBT];
#pragma unroll
        for (int n = 0; n < NBT; n++) m4[n] = a[n][i];
        fma9x4(acc, sS + i * ROWP, m4);
    }

    // ---- degree 2 (rows 9..53) + degree 3 (rows 54..218)
    int trow = 54;                                        // folded by full unroll
#pragma unroll
    for (int i = 0; i < 9; i++) {
#pragma unroll
        for (int j = i; j < 9; j++) {
            int pidx = i * 9 - (i * (i - 1)) / 2 + (j - i);
            float p4[NBT];
#pragma unroll
            for (int n = 0; n < NBT; n++) p4[n] = a[n][i] * a[n][j];
            fma9x4(acc, sS + (9 + pidx) * ROWP, p4);
#pragma unroll
            for (int l = j; l < 9; l++) {
                float m4[NBT];
#pragma unroll
                for (int n = 0; n < NBT; n++) m4[n] = p4[n] * a[n][l];
                fma9x4(acc, sS + trow * ROWP, m4);
                trow++;
            }
        }
    }

#pragma unroll
    for (int n = 0; n < NBT; n++) {
        float* op = out + ((bbase + n * BLK) * NC + c) * NI;
#pragma unroll
        for (int q = 0; q < 9; q++) op[q] = acc[n][q];
    }
}

// ---------------------------------------------------------------------------
// Launch: resolve inputs by element count (ordering-agnostic).
// ---------------------------------------------------------------------------
extern "C" void kernel_launch(void* const* d_in, const int* in_sizes, int n_in,
                              void* d_out, int out_size)
{
    const float* A = nullptr;
    const float* U[3][3] = {};   // [type s/p/d][nu-1]
    const float* W[3][3] = {};   // [type s/p/d][nu-1]

    int typeorder[3] = { 0, 1, 2 };
    int to_n = 0;
    int w1_idx[3]; int w1_n = 0;

    for (int idx = 0; idx < n_in; idx++) {
        int s = in_sizes[idx];
        const float* p = (const float*)d_in[idx];
        switch (s) {
            case NB * NC * NI: A = p; break;
            case 9:     U[0][0] = p; break;   // U_s1 (1,9,1)
            case 162:   U[0][1] = p; break;   // U_s2 (1,9,9,2)
            case 3645:  U[0][2] = p; break;   // U_s3 (1,9,9,9,5)
            case 27:    U[1][0] = p; break;   // U_p1 (3,9,1)
            case 729:   U[1][1] = p; break;   // U_p2 (3,9,9,3)
            case 17496: U[1][2] = p; break;   // U_p3 (3,9,9,9,8)
            case 45:    U[2][0] = p; break;   // U_d1 (5,9,1)
            case 1620:  U[2][1] = p; break;   // U_d2 (5,9,9,4)
            case 36450: U[2][2] = p; break;   // U_d3 (5,9,9,9,10)
            case 256:   W[0][1] = p; if (to_n < 3) typeorder[to_n++] = 0; break; // w_s2
            case 384:   W[1][1] = p; if (to_n < 3) typeorder[to_n++] = 1; break; // w_p2
            case 512:   W[2][1] = p; if (to_n < 3) typeorder[to_n++] = 2; break; // w_d2
            case 640:   W[0][2] = p; break;   // w_s3
            case 1024:  W[1][2] = p; break;   // w_p3
            case 1280:  W[2][2] = p; break;   // w_d3
            case 128:   if (w1_n < 3) w1_idx[w1_n++] = idx; break; // w_*1 (ambiguous)
            default: break;
        }
    }
    for (int q = 0; q < 3 && q < w1_n; q++)
        W[typeorder[q]][0] = (const float*)d_in[w1_idx[q]];

    // Stage 1: symmetrize U (c-independent), one thread per output scalar
    {
        int jobs = 45 * 9 * 4 + 165 * 9 * 10;   // 16470
        symU_kernel<<<(jobs + 255) / 256, 256>>>(
            U[0][1], U[1][1], U[2][1],
            U[0][2], U[1][2], U[2][2]);
    }

    // Stage 2: contract with w -> per-channel S
    {
        int jobs = NT * NC;
        buildS_kernel<<<(jobs + 255) / 256, 256>>>(
            U[0][0], U[1][0], U[2][0],
            W[0][0], W[0][1], W[0][2],
            W[1][0], W[1][1], W[1][2],
            W[2][0], W[2][1], W[2][2]);
    }

    // Stage 3: main contraction, 4 nodes per thread, 1024 balanced blocks
    dim3 grid(NC, NB / (BLK * NBT));
    sc_main_kernel<<<grid, BLK>>>(A, (float*)d_out);
}

// round 4
// speedup vs baseline: 1.5318x; 1.4385x over previous
#include <cuda_runtime.h>

// ---------------------------------------------------------------------------
// SymmetricContraction: out[b,c,m] = cubic polynomial in A[b,c,0..8]
// Stage 1 (prep): S[c][t][m] = sum_k Usym[t][m][k] * w_k[c], with Usym the
//                 perm-symmetrized U folded with multiset multiplicities.
//                 One thread per (t,m,c) scalar -> high occupancy, fused.
// Stage 2 (main): out[b,c,m] = sum_t S[c][t][m] * mono_t(A[b,c,:])
//                 BLK=128 threads, NBT=2 nodes/thread (register-safe:
//                 ~60 live floats so row LDS are NOT rematerialized).
// ---------------------------------------------------------------------------

#define NC 128        // channels
#define NB 2048       // nodes
#define NI 9          // irreps dim
#define NT 219        // 9 singles + 45 pairs + 165 triples
#define ROWP 12       // padded row (floats) -> 48B
#define NBT 2         // nodes per thread
#define BLK 128       // threads per main block

#define NROW2 (45 * 9)     // deg-2 (tp, m) jobs
#define NROW3 (165 * 9)    // deg-3 (tp, m) jobs
#define NROWS (9 + NROW2 + NROW3)   // 1899 job rows

static __device__ float g_S[NC * NT * ROWP];       // ~1.35 MB

// ---------------------------------------------------------------------------
// Kernel 1: fused prep. gid = jobrow * NC + c.
//   jobrow <   9            : degree-1 row t (computes all 9 m, zeros pad)
//   jobrow <   9+NROW2      : degree-2 scalar (tp, m)
//   else                    : degree-3 scalar (tp, m)
// U loads are warp-uniform (same jobrow across warp) -> L1 broadcast;
// w loads are coalesced over c.
// ---------------------------------------------------------------------------
__global__ void prep_kernel(
    const float* __restrict__ Us1, const float* __restrict__ Up1, const float* __restrict__ Ud1,
    const float* __restrict__ Us2, const float* __restrict__ Up2, const float* __restrict__ Ud2,
    const float* __restrict__ Us3, const float* __restrict__ Up3, const float* __restrict__ Ud3,
    const float* __restrict__ ws1, const float* __restrict__ ws2, const float* __restrict__ ws3,
    const float* __restrict__ wp1, const float* __restrict__ wp2, const float* __restrict__ wp3,
    const float* __restrict__ wd1, const float* __restrict__ wd2, const float* __restrict__ wd3)
{
    int gid = blockIdx.x * blockDim.x + threadIdx.x;
    if (gid >= NROWS * NC) return;
    int c = gid % NC;
    int row = gid / NC;

    if (row < 9) {
        // degree-1: whole row t = row
        int t = row;
        float* dst = g_S + (c * NT + t) * ROWP;
        dst[0] = Us1[t] * ws1[c];
#pragma unroll
        for (int m = 0; m < 3; m++) dst[1 + m] = Up1[m * 9 + t] * wp1[c];
#pragma unroll
        for (int m = 0; m < 5; m++) dst[4 + m] = Ud1[m * 9 + t] * wd1[c];
        dst[9] = 0.f; dst[10] = 0.f; dst[11] = 0.f;
        return;
    }

    if (row < 9 + NROW2) {
        // degree-2 scalar: (tp, m)
        int r = row - 9;
        int m = r % 9, tp = r / 9;
        int t = 9 + tp;
        int rem = tp, i = 0, j = 0;
        for (i = 0; i < 9; i++) { int cnt = 9 - i; if (rem < cnt) { j = i + rem; break; } rem -= cnt; }
        float inv = (i == j) ? 0.5f : 1.0f;

        int K; const float* U; const float* w; int mm;
        if (m == 0)      { K = 2; U = Us2; w = ws2; mm = 0; }
        else if (m < 4)  { K = 3; U = Up2; w = wp2; mm = m - 1; }
        else             { K = 4; U = Ud2; w = wd2; mm = m - 4; }

        float s = 0.f;
        for (int k = 0; k < K; k++) {
            float u = U[((mm * 9 + i) * 9 + j) * K + k] + U[((mm * 9 + j) * 9 + i) * K + k];
            s += u * w[k * NC + c];
        }
        float* dst = g_S + (c * NT + t) * ROWP;
        dst[m] = s * inv;
        if (m < 3) dst[9 + m] = 0.f;    // zero the pad lanes
        return;
    }

    // degree-3 scalar: (tp, m)
    {
        int r = row - (9 + NROW2);
        int m = r % 9, tp = r / 9;
        int t = 54 + tp;
        int rem = tp, i = 0, j = 0, l = 0;
        for (i = 0; i < 9; i++) { int cnt = (9 - i) * (10 - i) / 2; if (rem < cnt) break; rem -= cnt; }
        for (j = i; j < 9; j++) { int cnt = 9 - j; if (rem < cnt) { l = j + rem; break; } rem -= cnt; }
        float inv;
        if (i == j && j == l)                 inv = 1.0f / 6.0f;
        else if (i == j || j == l || i == l)  inv = 0.5f;
        else                                  inv = 1.0f;

        int K; const float* U; const float* w; int mm;
        if (m == 0)      { K = 5;  U = Us3; w = ws3; mm = 0; }
        else if (m < 4)  { K = 8;  U = Up3; w = wp3; mm = m - 1; }
        else             { K = 10; U = Ud3; w = wd3; mm = m - 4; }

        int P0[6] = { i,i,j,j,l,l }, P1[6] = { j,l,i,l,i,j }, P2i[6] = { l,j,l,i,j,i };
        float s = 0.f;
        for (int k = 0; k < K; k++) {
            float u = 0.f;
#pragma unroll
            for (int p = 0; p < 6; p++)
                u += U[(((mm * 9 + P0[p]) * 9 + P1[p]) * 9 + P2i[p]) * K + k];
            s += u * w[k * NC + c];
        }
        float* dst = g_S + (c * NT + t) * ROWP;
        dst[m] = s * inv;
        if (m < 3) dst[9 + m] = 0.f;
    }
}

// ---------------------------------------------------------------------------
// Kernel 2: hot loop. BLK=128 threads, NBT=2 nodes/thread, grid (128, 8).
// Every smem row load (broadcast, conflict-free) feeds 18 FMAs.
// ---------------------------------------------------------------------------
__device__ __forceinline__ void fma9xN(float acc[NBT][9], const float* __restrict__ row,
                                       const float mN[NBT])
{
    float4 r0 = *reinterpret_cast<const float4*>(row);
    float4 r1 = *reinterpret_cast<const float4*>(row + 4);
    float  r8 = row[8];
#pragma unroll
    for (int n = 0; n < NBT; n++) {
        acc[n][0] = fmaf(r0.x, mN[n], acc[n][0]);
        acc[n][1] = fmaf(r0.y, mN[n], acc[n][1]);
        acc[n][2] = fmaf(r0.z, mN[n], acc[n][2]);
        acc[n][3] = fmaf(r0.w, mN[n], acc[n][3]);
        acc[n][4] = fmaf(r1.x, mN[n], acc[n][4]);
        acc[n][5] = fmaf(r1.y, mN[n], acc[n][5]);
        acc[n][6] = fmaf(r1.z, mN[n], acc[n][6]);
        acc[n][7] = fmaf(r1.w, mN[n], acc[n][7]);
        acc[n][8] = fmaf(r8,  mN[n], acc[n][8]);
    }
}

__global__ __launch_bounds__(BLK) void sc_main_kernel(
    const float* __restrict__ A, float* __restrict__ out)
{
    __shared__ __align__(16) float sS[NT * ROWP];

    int c = blockIdx.x;
    const float* gS = g_S + c * NT * ROWP;
    for (int idx = threadIdx.x; idx < NT * ROWP; idx += BLK)
        sS[idx] = gS[idx];
    __syncthreads();

    int bbase = blockIdx.y * (BLK * NBT) + threadIdx.x;   // nodes bbase + n*BLK

    float a[NBT][9];
#pragma unroll
    for (int n = 0; n < NBT; n++) {
        const float* Ap = A + ((bbase + n * BLK) * NC + c) * NI;
#pragma unroll
        for (int i = 0; i < 9; i++) a[n][i] = __ldg(Ap + i);
    }

    float acc[NBT][9];
#pragma unroll
    for (int n = 0; n < NBT; n++)
#pragma unroll
        for (int q = 0; q < 9; q++) acc[n][q] = 0.f;

    // ---- degree 1: rows 0..8
#pragma unroll
    for (int i = 0; i < 9; i++) {
        float mN[NBT];
#pragma unroll
        for (int n = 0; n < NBT; n++) mN[n] = a[n][i];
        fma9xN(acc, sS + i * ROWP, mN);
    }

    // ---- degree 2 (rows 9..53) + degree 3 (rows 54..218)
    int trow = 54;                                        // folded by full unroll
#pragma unroll
    for (int i = 0; i < 9; i++) {
#pragma unroll
        for (int j = i; j < 9; j++) {
            int pidx = i * 9 - (i * (i - 1)) / 2 + (j - i);
            float pN[NBT];
#pragma unroll
            for (int n = 0; n < NBT; n++) pN[n] = a[n][i] * a[n][j];
            fma9xN(acc, sS + (9 + pidx) * ROWP, pN);
#pragma unroll
            for (int l = j; l < 9; l++) {
                float mN[NBT];
#pragma unroll
                for (int n = 0; n < NBT; n++) mN[n] = pN[n] * a[n][l];
                fma9xN(acc, sS + trow * ROWP, mN);
                trow++;
            }
        }
    }

#pragma unroll
    for (int n = 0; n < NBT; n++) {
        float* op = out + ((bbase + n * BLK) * NC + c) * NI;
#pragma unroll
        for (int q = 0; q < 9; q++) op[q] = acc[n][q];
    }
}

// ---------------------------------------------------------------------------
// Launch: resolve inputs by element count (ordering-agnostic).
// ---------------------------------------------------------------------------
extern "C" void kernel_launch(void* const* d_in, const int* in_sizes, int n_in,
                              void* d_out, int out_size)
{
    const float* A = nullptr;
    const float* U[3][3] = {};   // [type s/p/d][nu-1]
    const float* W[3][3] = {};   // [type s/p/d][nu-1]

    int typeorder[3] = { 0, 1, 2 };
    int to_n = 0;
    int w1_idx[3]; int w1_n = 0;

    for (int idx = 0; idx < n_in; idx++) {
        int s = in_sizes[idx];
        const float* p = (const float*)d_in[idx];
        switch (s) {
            case NB * NC * NI: A = p; break;
            case 9:     U[0][0] = p; break;   // U_s1 (1,9,1)
            case 162:   U[0][1] = p; break;   // U_s2 (1,9,9,2)
            case 3645:  U[0][2] = p; break;   // U_s3 (1,9,9,9,5)
            case 27:    U[1][0] = p; break;   // U_p1 (3,9,1)
            case 729:   U[1][1] = p; break;   // U_p2 (3,9,9,3)
            case 17496: U[1][2] = p; break;   // U_p3 (3,9,9,9,8)
            case 45:    U[2][0] = p; break;   // U_d1 (5,9,1)
            case 1620:  U[2][1] = p; break;   // U_d2 (5,9,9,4)
            case 36450: U[2][2] = p; break;   // U_d3 (5,9,9,9,10)
            case 256:   W[0][1] = p; if (to_n < 3) typeorder[to_n++] = 0; break; // w_s2
            case 384:   W[1][1] = p; if (to_n < 3) typeorder[to_n++] = 1; break; // w_p2
            case 512:   W[2][1] = p; if (to_n < 3) typeorder[to_n++] = 2; break; // w_d2
            case 640:   W[0][2] = p; break;   // w_s3
            case 1024:  W[1][2] = p; break;   // w_p3
            case 1280:  W[2][2] = p; break;   // w_d3
            case 128:   if (w1_n < 3) w1_idx[w1_n++] = idx; break; // w_*1 (ambiguous)
            default: break;
        }
    }
    for (int q = 0; q < 3 && q < w1_n; q++)
        W[typeorder[q]][0] = (const float*)d_in[w1_idx[q]];

    // Stage 1: fused prep (symmetrize + w-contract), one thread per scalar row
    {
        int jobs = NROWS * NC;   // 1899 * 128
        prep_kernel<<<(jobs + 255) / 256, 256>>>(
            U[0][0], U[1][0], U[2][0],
            U[0][1], U[1][1], U[2][1],
            U[0][2], U[1][2], U[2][2],
            W[0][0], W[0][1], W[0][2],
            W[1][0], W[1][1], W[1][2],
            W[2][0], W[2][1], W[2][2]);
    }

    // Stage 2: main contraction, 2 nodes per thread, 1024 balanced blocks
    dim3 grid(NC, NB / (BLK * NBT));
    sc_main_kernel<<<grid, BLK>>>(A, (float*)d_out);
}